// round 15
// baseline (speedup 1.0000x reference)
#include <cuda_runtime.h>
#include <cuda_bf16.h>
#include <cstdint>
#include <math.h>

#define B_ 2
#define S_ 2048
#define C_ 2048
#define H_ 32
#define C3 6144
#define BS (B_*S_)

// Scratch (allocation-free device globals)
__device__ float g_qkv[BS * C3];
__device__ uint32_t g_xtf[(size_t)BS * C_];
__device__ uint32_t g_wqtf[(size_t)C3 * C_];
__device__ uint32_t g_wotf[(size_t)C_ * C_];
__device__ uint32_t g_atf[(size_t)BS * C_];
__device__ __nv_bfloat16 g_qhi[BS * C_],  g_qlo[BS * C_];
__device__ __nv_bfloat16 g_khi[BS * C_],  g_klo[BS * C_];
__device__ __nv_bfloat16 g_vthi[(size_t)B_ * H_ * 64 * S_], g_vtlo[(size_t)B_ * H_ * 64 * S_];

__device__ __forceinline__ void mma_bf16(float4 &d,
    uint32_t a0, uint32_t a1, uint32_t a2, uint32_t a3, uint32_t b0, uint32_t b1)
{
    asm volatile("mma.sync.aligned.m16n8k16.row.col.f32.bf16.bf16.f32 "
        "{%0,%1,%2,%3}, {%4,%5,%6,%7}, {%8,%9}, {%0,%1,%2,%3};"
        : "+f"(d.x), "+f"(d.y), "+f"(d.z), "+f"(d.w)
        : "r"(a0), "r"(a1), "r"(a2), "r"(a3), "r"(b0), "r"(b1));
}

__device__ __forceinline__ void mma_tf32(float4 &d,
    uint32_t a0, uint32_t a1, uint32_t a2, uint32_t a3, uint32_t b0, uint32_t b1)
{
    asm volatile("mma.sync.aligned.m16n8k8.row.col.f32.tf32.tf32.f32 "
        "{%0,%1,%2,%3}, {%4,%5,%6,%7}, {%8,%9}, {%0,%1,%2,%3};"
        : "+f"(d.x), "+f"(d.y), "+f"(d.z), "+f"(d.w)
        : "r"(a0), "r"(a1), "r"(a2), "r"(a3), "r"(b0), "r"(b1));
}

__device__ __forceinline__ uint32_t f2tf32(float x) {
    uint32_t r; asm("cvt.rna.tf32.f32 %0, %1;" : "=r"(r) : "f"(x)); return r;
}

__device__ __forceinline__ void cp16(uint32_t saddr, const void* g) {
    asm volatile("cp.async.cg.shared.global [%0], [%1], 16;" :: "r"(saddr), "l"(g));
}
#define CP_COMMIT() asm volatile("cp.async.commit_group;")

__device__ __forceinline__ uint32_t pack2(__nv_bfloat16 a, __nv_bfloat16 b) {
    __nv_bfloat162 t; t.x = a; t.y = b;
    return *reinterpret_cast<uint32_t*>(&t);
}

__device__ __forceinline__ void split2(float a, float b, uint32_t &hi, uint32_t &lo) {
    __nv_bfloat16 ha = __float2bfloat16_rn(a), hb = __float2bfloat16_rn(b);
    __nv_bfloat16 la = __float2bfloat16_rn(a - __bfloat162float(ha));
    __nv_bfloat16 lb = __float2bfloat16_rn(b - __bfloat162float(hb));
    hi = pack2(ha, hb); lo = pack2(la, lb);
}

// fp32 -> tf32 converter
__global__ __launch_bounds__(256) void cvt_tf32_kernel(
    const float* __restrict__ in, uint32_t* __restrict__ out, int n4)
{
    int i = blockIdx.x * blockDim.x + threadIdx.x;
    if (i >= n4) return;
    float4 v = ((const float4*)in)[i];
    ((uint4*)out)[i] = make_uint4(f2tf32(v.x), f2tf32(v.y), f2tf32(v.z), f2tf32(v.w));
}

// ---------------------------------------------------------------------------
// tf32 GEMM: C[m][n] = sum_k A[m][k]*B[n][k], operands pre-converted tf32.
// Block 128x128, BK=32, 256 thr = 8 warps (2m x 4n), warp 64x32, 2 CTAs/SM.
// Smem row pitch 36 words (144B): frag-load bank = (4g + c) mod 32, conflict-
// free. 3-stage cp.async, single barrier per iter (R12 pipeline).
// ---------------------------------------------------------------------------
#define TSTAGES 3
#define TTILEB (128 * 36 * 4)          // 18432 B per operand tile
#define TSTAGE_BYTES (2 * TTILEB)      // 36864
#define TGEMM_SMEM (TSTAGES * TSTAGE_BYTES)   // 110592

__global__ __launch_bounds__(256, 2) void gemm_tf32(
    const uint32_t* __restrict__ At, const uint32_t* __restrict__ Bt,
    float* __restrict__ C, int M, int N, int K)
{
    extern __shared__ uint8_t tsm8[];
    uint32_t* sw = (uint32_t*)tsm8;
    const uint32_t sbase = (uint32_t)__cvta_generic_to_shared(tsm8);

    const int tid = threadIdx.x, lane = tid & 31, wid = tid >> 5;
    const int g = lane >> 2, c = lane & 3;
    const int wm = wid >> 2, wn = wid & 3;
    const int m0 = blockIdx.y * 128, n0 = blockIdx.x * 128;

    // cp.async mapping: thread -> (row, 4 of 8 chunks)
    const int crow = tid >> 1;
    const int ch0  = (tid & 1) * 4;
    const uint32_t soffA = crow * 144 + ch0 * 16;
    const uint4* gA = (const uint4*)At + (((size_t)(m0 + crow) * K) >> 2) + ch0;
    const uint4* gB = (const uint4*)Bt + (((size_t)(n0 + crow) * K) >> 2) + ch0;

    float4 d[4][4];
#pragma unroll
    for (int i = 0; i < 4; i++)
#pragma unroll
        for (int j = 0; j < 4; j++) d[i][j] = make_float4(0.f, 0.f, 0.f, 0.f);

    auto issue = [&](int tile) {
        const uint32_t sb = sbase + (tile % TSTAGES) * TSTAGE_BYTES;
        const int kc = tile * 8;                 // uint4 chunks per BK32
#pragma unroll
        for (int j = 0; j < 4; j++) {
            cp16(sb + soffA + j * 16,          gA + kc + j);
            cp16(sb + TTILEB + soffA + j * 16, gB + kc + j);
        }
    };

    const int nit = K >> 5;
    issue(0); CP_COMMIT();
    issue(1); CP_COMMIT();

    for (int it = 0; it < nit; it++) {
        if (it + 1 < nit) { asm volatile("cp.async.wait_group 1;"); }
        else              { asm volatile("cp.async.wait_group 0;"); }
        __syncthreads();
        if (it + 2 < nit) { issue(it + 2); CP_COMMIT(); }

        const uint32_t* SA = sw + (it % TSTAGES) * (TSTAGE_BYTES / 4);
        const uint32_t* SB = SA + 128 * 36;

#pragma unroll
        for (int ks = 0; ks < 4; ks++) {
            uint32_t b0[4], b1[4];
#pragma unroll
            for (int in_ = 0; in_ < 4; in_++) {
                int n = wn * 32 + in_ * 8 + g;
                b0[in_] = SB[n * 36 + 8 * ks + c];
                b1[in_] = SB[n * 36 + 8 * ks + c + 4];
            }
#pragma unroll
            for (int im = 0; im < 4; im++) {
                int r = wm * 64 + im * 16 + g;
                uint32_t a0 = SA[r * 36 + 8 * ks + c];
                uint32_t a1 = SA[(r + 8) * 36 + 8 * ks + c];
                uint32_t a2 = SA[r * 36 + 8 * ks + c + 4];
                uint32_t a3 = SA[(r + 8) * 36 + 8 * ks + c + 4];
#pragma unroll
                for (int in_ = 0; in_ < 4; in_++)
                    mma_tf32(d[im][in_], a0, a1, a2, a3, b0[in_], b1[in_]);
            }
        }
    }

#pragma unroll
    for (int im = 0; im < 4; im++)
#pragma unroll
        for (int in_ = 0; in_ < 4; in_++) {
            int row = m0 + wm * 64 + im * 16 + g;
            int col = n0 + wn * 32 + in_ * 8 + 2 * c;
            *(float2*)&C[(size_t)row * N + col]       = make_float2(d[im][in_].x, d[im][in_].y);
            *(float2*)&C[(size_t)(row + 8) * N + col] = make_float2(d[im][in_].z, d[im][in_].w);
        }
}

// ---------------------------------------------------------------------------
// LN (per-head) + rotary; q pre-scaled by 1/8; writes split bf16 q/k (R7).
// ---------------------------------------------------------------------------
__global__ __launch_bounds__(256) void ln_rope_kernel(
    const float* __restrict__ qkv, const float* __restrict__ rope,
    const float* __restrict__ qg, const float* __restrict__ qb,
    const float* __restrict__ kg, const float* __restrict__ kb,
    __nv_bfloat16* __restrict__ qhi, __nv_bfloat16* __restrict__ qlo,
    __nv_bfloat16* __restrict__ khi, __nv_bfloat16* __restrict__ klo)
{
    int wid  = (blockIdx.x * blockDim.x + threadIdx.x) >> 5;
    int lane = threadIdx.x & 31;
    int which = wid & 1;
    int rowh  = wid >> 1;
    int h  = rowh & 31;
    int bs = rowh >> 5;
    int s  = bs & (S_ - 1);

    const float* p = qkv + (size_t)bs * C3 + h * 192 + which * 64;
    float x0 = p[lane];
    float x1 = p[lane + 32];

    float sum = x0 + x1;
#pragma unroll
    for (int off = 16; off > 0; off >>= 1) sum += __shfl_xor_sync(0xffffffffu, sum, off);
    float mean = sum * (1.0f / 64.0f);
    float d0 = x0 - mean, d1 = x1 - mean;
    float vs = d0 * d0 + d1 * d1;
#pragma unroll
    for (int off = 16; off > 0; off >>= 1) vs += __shfl_xor_sync(0xffffffffu, vs, off);
    float rstd = rsqrtf(vs * (1.0f / 64.0f) + 1e-5f);

    const float* gm = which ? kg : qg;
    const float* bt = which ? kb : qb;
    float y0 = d0 * rstd * gm[lane]      + bt[lane];
    float y1 = d1 * rstd * gm[lane + 32] + bt[lane + 32];

    float pr0 = __shfl_xor_sync(0xffffffffu, y0, 1);
    float pr1 = __shfl_xor_sync(0xffffffffu, y1, 1);
    int j = lane & 1;
    const float* rb = rope + s * 128;

    int i0 = lane >> 1;
    float e0 = j ? pr0 : y0;
    float o0 = j ? y0 : pr0;
    float out0 = rb[i0 * 4 + j * 2 + 0] * e0 + rb[i0 * 4 + j * 2 + 1] * o0;

    int i1 = (lane + 32) >> 1;
    float e1 = j ? pr1 : y1;
    float o1 = j ? y1 : pr1;
    float out1 = rb[i1 * 4 + j * 2 + 0] * e1 + rb[i1 * 4 + j * 2 + 1] * o1;

    if (which == 0) { out0 *= 0.125f; out1 *= 0.125f; }

    __nv_bfloat16* hi = which ? khi : qhi;
    __nv_bfloat16* lo = which ? klo : qlo;
    size_t base = (size_t)bs * C_ + h * 64;
    __nv_bfloat16 h0 = __float2bfloat16_rn(out0);
    __nv_bfloat16 h1 = __float2bfloat16_rn(out1);
    hi[base + lane]      = h0;
    hi[base + lane + 32] = h1;
    lo[base + lane]      = __float2bfloat16_rn(out0 - __bfloat162float(h0));
    lo[base + lane + 32] = __float2bfloat16_rn(out1 - __bfloat162float(h1));
}

// ---------------------------------------------------------------------------
// V transpose + split: qkv v-slice [b][s][h][d] -> vt[b][h][d][s] bf16 hi/lo
// ---------------------------------------------------------------------------
__global__ __launch_bounds__(256) void vt_kernel(
    const float* __restrict__ qkv,
    __nv_bfloat16* __restrict__ vthi, __nv_bfloat16* __restrict__ vtlo)
{
    __shared__ __nv_bfloat16 shi[64][72];
    __shared__ __nv_bfloat16 slo[64][72];

    const int tid = threadIdx.x;
    const int s0 = blockIdx.x * 64, h = blockIdx.y, b = blockIdx.z;
    const int tok = tid >> 2, q = tid & 3;

#pragma unroll
    for (int it = 0; it < 4; it++) {
        int dd = q * 16 + it * 4;
        float4 v = *(const float4*)&qkv[(size_t)(b * S_ + s0 + tok) * C3 + h * 192 + 128 + dd];
        float vv[4] = {v.x, v.y, v.z, v.w};
#pragma unroll
        for (int j = 0; j < 4; j++) {
            __nv_bfloat16 hb = __float2bfloat16_rn(vv[j]);
            shi[dd + j][tok] = hb;
            slo[dd + j][tok] = __float2bfloat16_rn(vv[j] - __bfloat162float(hb));
        }
    }
    __syncthreads();

    const int dr = tid >> 2, cq = tid & 3;
    size_t gbase = ((size_t)(b * H_ + h) * 64 + dr) * S_ + s0 + cq * 16;
#pragma unroll
    for (int half = 0; half < 2; half++) {
        *(uint4*)&vthi[gbase + half * 8] = *(const uint4*)&shi[dr][cq * 16 + half * 8];
        *(uint4*)&vtlo[gbase + half * 8] = *(const uint4*)&slo[dr][cq * 16 + half * 8];
    }
}

// ---------------------------------------------------------------------------
// Flash attention, bf16x3 (R7-verified math), cp.async double-buffered,
// 2 CTAs/SM. Epilogue writes tf32 att directly for the tf32 out-projection.
// ---------------------------------------------------------------------------
#define SW(row, ch) ((row) * 32 + (((ch) ^ ((row) & 7)) << 2))
#define ATT_SMEM (2 * 4 * 8192)

__global__ __launch_bounds__(256, 2) void attn_bf16x3(
    const __nv_bfloat16* __restrict__ qhi, const __nv_bfloat16* __restrict__ qlo,
    const __nv_bfloat16* __restrict__ khi, const __nv_bfloat16* __restrict__ klo,
    const __nv_bfloat16* __restrict__ vthi, const __nv_bfloat16* __restrict__ vtlo,
    uint32_t* __restrict__ atf)
{
    extern __shared__ uint8_t asm8[];
    uint32_t* dsmw = (uint32_t*)asm8;
    const uint32_t sabase = (uint32_t)__cvta_generic_to_shared(asm8);

    const int tid = threadIdx.x, lane = tid & 31, wid = tid >> 5;
    const int g = lane >> 2, c = lane & 3;
    const int q0 = blockIdx.x * 128;
    const int h = blockIdx.y, b = blockIdx.z;
    const int w16 = wid * 16;

    const uint32_t* qh32 = (const uint32_t*)qhi;
    const uint32_t* ql32 = (const uint32_t*)qlo;
    size_t r0 = (size_t)(b * S_ + q0 + w16 + g) * 1024 + h * 32;
    size_t r1 = r0 + 8 * 1024;
    uint32_t Qh[4][4], Ql[4][4];
#pragma unroll
    for (int s = 0; s < 4; s++) {
        int w0 = 8 * s + c;
        Qh[s][0] = qh32[r0 + w0];     Qh[s][1] = qh32[r1 + w0];
        Qh[s][2] = qh32[r0 + w0 + 4]; Qh[s][3] = qh32[r1 + w0 + 4];
        Ql[s][0] = ql32[r0 + w0];     Ql[s][1] = ql32[r1 + w0];
        Ql[s][2] = ql32[r0 + w0 + 4]; Ql[s][3] = ql32[r1 + w0 + 4];
    }

    const uint4* kh4 = (const uint4*)khi;
    const uint4* kl4 = (const uint4*)klo;
    const uint4* vh4 = (const uint4*)vthi;
    const uint4* vl4 = (const uint4*)vtlo;

    float m_lo = -1e30f, m_hi = -1e30f, l_lo = 0.f, l_hi = 0.f;
    float4 acc[8];
#pragma unroll
    for (int nt = 0; nt < 8; nt++) acc[nt] = make_float4(0.f, 0.f, 0.f, 0.f);

    const int trow = tid & 63;
    const int tch0 = tid >> 6;

    auto issueA = [&](int i) {
        const uint32_t sb = sabase + (i & 1) * 32768;
        const int kv0 = i * 64;
        const size_t kg = (size_t)(b * S_ + kv0 + trow) * 256 + h * 8;
        const size_t vg = ((size_t)(b * H_ + h) * 64 + trow) * 256 + (size_t)(kv0 >> 3);
#pragma unroll
        for (int p = 0; p < 2; p++) {
            const int ch = tch0 + 4 * p;
            const uint32_t so = trow * 128 + ((ch ^ (trow & 7)) << 4);
            cp16(sb + so,         kh4 + kg + ch);
            cp16(sb + 8192  + so, kl4 + kg + ch);
            cp16(sb + 16384 + so, vh4 + vg + ch);
            cp16(sb + 24576 + so, vl4 + vg + ch);
        }
    };

    issueA(0); CP_COMMIT();

    for (int i = 0; i < 32; i++) {
        asm volatile("cp.async.wait_group 0;");
        __syncthreads();
        if (i + 1 < 32) { issueA(i + 1); CP_COMMIT(); }

        const uint32_t* sKh = dsmw + ((i & 1) * 4 + 0) * 2048;
        const uint32_t* sKl = dsmw + ((i & 1) * 4 + 1) * 2048;
        const uint32_t* sVh = dsmw + ((i & 1) * 4 + 2) * 2048;
        const uint32_t* sVl = dsmw + ((i & 1) * 4 + 3) * 2048;

        float4 sf[8];
#pragma unroll
        for (int nt = 0; nt < 8; nt++) sf[nt] = make_float4(0.f, 0.f, 0.f, 0.f);
#pragma unroll
        for (int s = 0; s < 4; s++) {
#pragma unroll
            for (int nt = 0; nt < 8; nt++) {
                int n = nt * 8 + g;
                uint32_t bh0 = sKh[SW(n, 2*s) + c],   bh1 = sKh[SW(n, 2*s+1) + c];
                uint32_t bl0 = sKl[SW(n, 2*s) + c],   bl1 = sKl[SW(n, 2*s+1) + c];
                mma_bf16(sf[nt], Qh[s][0], Qh[s][1], Qh[s][2], Qh[s][3], bh0, bh1);
                mma_bf16(sf[nt], Qh[s][0], Qh[s][1], Qh[s][2], Qh[s][3], bl0, bl1);
                mma_bf16(sf[nt], Ql[s][0], Ql[s][1], Ql[s][2], Ql[s][3], bh0, bh1);
            }
        }

        float tlo = -1e30f, thi = -1e30f;
#pragma unroll
        for (int nt = 0; nt < 8; nt++) {
            tlo = fmaxf(tlo, fmaxf(sf[nt].x, sf[nt].y));
            thi = fmaxf(thi, fmaxf(sf[nt].z, sf[nt].w));
        }
        tlo = fmaxf(tlo, __shfl_xor_sync(0xffffffffu, tlo, 1));
        tlo = fmaxf(tlo, __shfl_xor_sync(0xffffffffu, tlo, 2));
        thi = fmaxf(thi, __shfl_xor_sync(0xffffffffu, thi, 1));
        thi = fmaxf(thi, __shfl_xor_sync(0xffffffffu, thi, 2));

        float mnlo = fmaxf(m_lo, tlo), mnhi = fmaxf(m_hi, thi);
        float corlo = __expf(m_lo - mnlo), corhi = __expf(m_hi - mnhi);
        float slo = 0.f, shi = 0.f;
#pragma unroll
        for (int nt = 0; nt < 8; nt++) {
            sf[nt].x = __expf(sf[nt].x - mnlo);
            sf[nt].y = __expf(sf[nt].y - mnlo);
            sf[nt].z = __expf(sf[nt].z - mnhi);
            sf[nt].w = __expf(sf[nt].w - mnhi);
            slo += sf[nt].x + sf[nt].y;
            shi += sf[nt].z + sf[nt].w;
        }
        slo += __shfl_xor_sync(0xffffffffu, slo, 1);
        slo += __shfl_xor_sync(0xffffffffu, slo, 2);
        shi += __shfl_xor_sync(0xffffffffu, shi, 1);
        shi += __shfl_xor_sync(0xffffffffu, shi, 2);
        l_lo = l_lo * corlo + slo;
        l_hi = l_hi * corhi + shi;
        m_lo = mnlo; m_hi = mnhi;
#pragma unroll
        for (int nt = 0; nt < 8; nt++) {
            acc[nt].x *= corlo; acc[nt].y *= corlo;
            acc[nt].z *= corhi; acc[nt].w *= corhi;
        }

#pragma unroll
        for (int s = 0; s < 4; s++) {
            uint32_t ah0, al0, ah1, al1, ah2, al2, ah3, al3;
            split2(sf[2*s].x,   sf[2*s].y,   ah0, al0);
            split2(sf[2*s].z,   sf[2*s].w,   ah1, al1);
            split2(sf[2*s+1].x, sf[2*s+1].y, ah2, al2);
            split2(sf[2*s+1].z, sf[2*s+1].w, ah3, al3);
#pragma unroll
            for (int nt = 0; nt < 8; nt++) {
                int n = nt * 8 + g;
                uint32_t vh0 = sVh[SW(n, 2*s) + c], vh1 = sVh[SW(n, 2*s+1) + c];
                uint32_t vl0 = sVl[SW(n, 2*s) + c], vl1 = sVl[SW(n, 2*s+1) + c];
                mma_bf16(acc[nt], ah0, ah1, ah2, ah3, vh0, vh1);
                mma_bf16(acc[nt], ah0, ah1, ah2, ah3, vl0, vl1);
                mma_bf16(acc[nt], al0, al1, al2, al3, vh0, vh1);
            }
        }
    }

    // epilogue: normalize + write tf32 att for tf32 out-projection
    float ilo = 1.f / l_lo, ihi = 1.f / l_hi;
    size_t ob0 = (size_t)(b * S_ + q0 + w16 + g) * 2048 + h * 64;
    size_t ob1 = ob0 + (size_t)8 * 2048;
#pragma unroll
    for (int nt = 0; nt < 8; nt++) {
        atf[ob0 + nt * 8 + 2 * c]     = f2tf32(acc[nt].x * ilo);
        atf[ob0 + nt * 8 + 2 * c + 1] = f2tf32(acc[nt].y * ilo);
        atf[ob1 + nt * 8 + 2 * c]     = f2tf32(acc[nt].z * ihi);
        atf[ob1 + nt * 8 + 2 * c + 1] = f2tf32(acc[nt].w * ihi);
    }
}

// ---------------------------------------------------------------------------
extern "C" void kernel_launch(void* const* d_in, const int* in_sizes, int n_in,
                              void* d_out, int out_size)
{
    const float* x     = (const float*)d_in[0];
    const float* rope  = (const float*)d_in[1];
    const float* w_qkv = (const float*)d_in[2];
    const float* w_out = (const float*)d_in[3];
    const float* qg    = (const float*)d_in[4];
    const float* qb    = (const float*)d_in[5];
    const float* kg    = (const float*)d_in[6];
    const float* kb    = (const float*)d_in[7];
    float* out = (float*)d_out;

    cudaFuncSetAttribute(gemm_tf32, cudaFuncAttributeMaxDynamicSharedMemorySize, TGEMM_SMEM);
    cudaFuncSetAttribute(attn_bf16x3, cudaFuncAttributeMaxDynamicSharedMemorySize, ATT_SMEM);

    float* qkv; cudaGetSymbolAddress((void**)&qkv, g_qkv);
    uint32_t *xtf, *wqtf, *wotf, *atf;
    __nv_bfloat16 *qhi, *qlo, *khi, *klo, *vthi, *vtlo;
    cudaGetSymbolAddress((void**)&xtf,  g_xtf);
    cudaGetSymbolAddress((void**)&wqtf, g_wqtf);
    cudaGetSymbolAddress((void**)&wotf, g_wotf);
    cudaGetSymbolAddress((void**)&atf,  g_atf);
    cudaGetSymbolAddress((void**)&qhi,  g_qhi);  cudaGetSymbolAddress((void**)&qlo,  g_qlo);
    cudaGetSymbolAddress((void**)&khi,  g_khi);  cudaGetSymbolAddress((void**)&klo,  g_klo);
    cudaGetSymbolAddress((void**)&vthi, g_vthi); cudaGetSymbolAddress((void**)&vtlo, g_vtlo);

    // 0) convert inputs/weights to tf32
    cvt_tf32_kernel<<<(BS * C_ / 4) / 256, 256>>>(x, xtf, BS * C_ / 4);
    cvt_tf32_kernel<<<(C3 * C_ / 4) / 256, 256>>>(w_qkv, wqtf, C3 * C_ / 4);
    cvt_tf32_kernel<<<(C_ * C_ / 4) / 256, 256>>>(w_out, wotf, C_ * C_ / 4);

    // 1) QKV projection (tf32 -> fp32 qkv)
    gemm_tf32<<<dim3(C3 / 128, BS / 128), 256, TGEMM_SMEM>>>(
        xtf, wqtf, qkv, BS, C3, C_);

    // 2) LN + rotary -> split bf16 q/k (q pre-scaled by 1/8)
    ln_rope_kernel<<<(BS * H_ * 2) / 8, 256>>>(qkv, rope, qg, qb, kg, kb, qhi, qlo, khi, klo);

    // 3) V transpose + split
    vt_kernel<<<dim3(S_ / 64, H_, B_), 256>>>(qkv, vthi, vtlo);

    // 4) flash attention (bf16x3) -> tf32 att
    attn_bf16x3<<<dim3(S_ / 128, H_, B_), 256, ATT_SMEM>>>(
        qhi, qlo, khi, klo, vthi, vtlo, atf);

    // 5) output projection (tf32)
    gemm_tf32<<<dim3(C_ / 128, BS / 128), 256, TGEMM_SMEM>>>(
        atf, wotf, out, BS, C_, C_);
}